// round 1
// baseline (speedup 1.0000x reference)
#include <cuda_runtime.h>

constexpr int kN = 100000;
constexpr int kE = 1600000;
constexpr int kG = 2048;
constexpr int kD = 128;
constexpr int kScanBlocks = (kN + 1023) / 1024; // 98

// ---------------- scratch (no allocations allowed) ----------------
__device__ float g_bufA[kN * kD];     // 51.2 MB
__device__ float g_bufB[kN * kD];     // 51.2 MB
__device__ float g_inv_src[kN];
__device__ float g_inv_dst[kN];
__device__ int   g_deg_out[kN];
__device__ int   g_deg_in[kN];
__device__ int   g_row_ptr[kN + 1];
__device__ int   g_cursor[kN];
__device__ int   g_edge_src[kE];      // src ids grouped by dst (CSR)
__device__ int   g_blk[kScanBlocks];
__device__ float g_emb[kG * kD];
__device__ int   g_gcnt[kG];
__device__ float g_x1[kG * 512];
__device__ float g_x2[kG * 256];

// ---------------- setup kernels ----------------
__global__ void k_zero_deg() {
    int i = blockIdx.x * blockDim.x + threadIdx.x;
    if (i < kN) { g_deg_out[i] = 0; g_deg_in[i] = 0; }
}

__global__ void k_degrees(const int* __restrict__ src, const int* __restrict__ dst) {
    int e = blockIdx.x * blockDim.x + threadIdx.x;
    if (e >= kE) return;
    atomicAdd(&g_deg_out[src[e]], 1);
    atomicAdd(&g_deg_in[dst[e]], 1);
}

__global__ void k_inv() {
    int i = blockIdx.x * blockDim.x + threadIdx.x;
    if (i >= kN) return;
    g_inv_src[i] = rsqrtf((float)max(g_deg_out[i], 1));
    g_inv_dst[i] = rsqrtf((float)max(g_deg_in[i], 1));
}

// exclusive scan of g_deg_in -> g_row_ptr (per-1024 partials), totals -> g_blk
__global__ void k_scan1() {
    __shared__ int sm[1024];
    int tid = threadIdx.x;
    int i = blockIdx.x * 1024 + tid;
    int v = (i < kN) ? g_deg_in[i] : 0;
    int x = v;
    sm[tid] = x;
    __syncthreads();
    for (int off = 1; off < 1024; off <<= 1) {
        int y = (tid >= off) ? sm[tid - off] : 0;
        __syncthreads();
        x += y;
        sm[tid] = x;
        __syncthreads();
    }
    if (i < kN) g_row_ptr[i] = x - v;
    if (tid == 1023) g_blk[blockIdx.x] = x;
}

__global__ void k_scan_tops() { // single block of 1024
    __shared__ int sm[1024];
    int tid = threadIdx.x;
    int v = (tid < kScanBlocks) ? g_blk[tid] : 0;
    int x = v;
    sm[tid] = x;
    __syncthreads();
    for (int off = 1; off < 1024; off <<= 1) {
        int y = (tid >= off) ? sm[tid - off] : 0;
        __syncthreads();
        x += y;
        sm[tid] = x;
        __syncthreads();
    }
    if (tid < kScanBlocks) g_blk[tid] = x - v;
}

__global__ void k_scan_add() {
    int i = blockIdx.x * blockDim.x + threadIdx.x;
    if (i < kN) {
        int rp = g_row_ptr[i] + g_blk[i >> 10];
        g_row_ptr[i] = rp;
        g_cursor[i]  = rp;
    }
    if (i == 0) g_row_ptr[kN] = kE;
}

__global__ void k_scatter(const int* __restrict__ src, const int* __restrict__ dst) {
    int e = blockIdx.x * blockDim.x + threadIdx.x;
    if (e >= kE) return;
    int d = dst[e];
    int pos = atomicAdd(&g_cursor[d], 1);
    g_edge_src[pos] = src[e];
}

// ---------------- GCN aggregation: one warp per dst node ----------------
// m[v] = inv_dst[v] * sum_{e in CSR(v)} inv_src[src_e] * h[src_e]
__global__ void k_gather(const float* __restrict__ h, float* __restrict__ m) {
    int w = (blockIdx.x * blockDim.x + threadIdx.x) >> 5;
    int lane = threadIdx.x & 31;
    if (w >= kN) return;
    int e0 = g_row_ptr[w];
    int e1 = g_row_ptr[w + 1];
    float4 acc = make_float4(0.f, 0.f, 0.f, 0.f);
    for (int e = e0; e < e1; ++e) {
        int s = g_edge_src[e];
        float ws = g_inv_src[s];
        float4 x = reinterpret_cast<const float4*>(h + (size_t)s * kD)[lane];
        acc.x += ws * x.x; acc.y += ws * x.y; acc.z += ws * x.z; acc.w += ws * x.w;
    }
    float wd = g_inv_dst[w];
    acc.x *= wd; acc.y *= wd; acc.z *= wd; acc.w *= wd;
    reinterpret_cast<float4*>(m + (size_t)w * kD)[lane] = acc;
}

// ---------------- [rows,128] x [128,128] + bias, ReLU ----------------
// 64-row tile per block, 256 threads, 8x4 register blocking.
constexpr int kGemmSmemBytes = (128 * 128 + 128 * 66) * 4; // 99328

__global__ void __launch_bounds__(256)
k_gemm128(const float* __restrict__ A, const float* __restrict__ W,
          const float* __restrict__ b, float* __restrict__ C, int rows) {
    extern __shared__ float sm[];
    float* Ws = sm;                   // [128][128]
    float* As = sm + 128 * 128;       // [128][66], k-major (padded)
    int t = threadIdx.x;
    int row0 = blockIdx.x * 64;

    const float4* W4 = reinterpret_cast<const float4*>(W);
    float4* Ws4 = reinterpret_cast<float4*>(Ws);
    #pragma unroll 4
    for (int i = t; i < 128 * 128 / 4; i += 256) Ws4[i] = W4[i];

    for (int i = t; i < 64 * 128 / 4; i += 256) {
        int r  = i >> 5;            // 0..63
        int kc = (i & 31) * 4;      // 0..124
        int gr = row0 + r;
        float4 v = make_float4(0.f, 0.f, 0.f, 0.f);
        if (gr < rows) v = reinterpret_cast<const float4*>(A + (size_t)gr * 128)[i & 31];
        As[(kc + 0) * 66 + r] = v.x;
        As[(kc + 1) * 66 + r] = v.y;
        As[(kc + 2) * 66 + r] = v.z;
        As[(kc + 3) * 66 + r] = v.w;
    }
    __syncthreads();

    int rg = t >> 5;            // warp id 0..7 -> rows rg*8..+7
    int cg = (t & 31) * 4;      // cols

    float acc[8][4];
    #pragma unroll
    for (int i = 0; i < 8; ++i)
        #pragma unroll
        for (int j = 0; j < 4; ++j) acc[i][j] = 0.f;

    #pragma unroll 4
    for (int k = 0; k < 128; ++k) {
        float4 w4 = *reinterpret_cast<const float4*>(&Ws[k * 128 + cg]);
        const float2* ap = reinterpret_cast<const float2*>(&As[k * 66 + rg * 8]);
        #pragma unroll
        for (int i2 = 0; i2 < 4; ++i2) {
            float2 a2 = ap[i2];
            acc[2 * i2 + 0][0] += a2.x * w4.x;
            acc[2 * i2 + 0][1] += a2.x * w4.y;
            acc[2 * i2 + 0][2] += a2.x * w4.z;
            acc[2 * i2 + 0][3] += a2.x * w4.w;
            acc[2 * i2 + 1][0] += a2.y * w4.x;
            acc[2 * i2 + 1][1] += a2.y * w4.y;
            acc[2 * i2 + 1][2] += a2.y * w4.z;
            acc[2 * i2 + 1][3] += a2.y * w4.w;
        }
    }

    float4 bb = *reinterpret_cast<const float4*>(&b[cg]);
    #pragma unroll
    for (int i = 0; i < 8; ++i) {
        int row = row0 + rg * 8 + i;
        if (row < rows) {
            float4 o;
            o.x = fmaxf(acc[i][0] + bb.x, 0.f);
            o.y = fmaxf(acc[i][1] + bb.y, 0.f);
            o.z = fmaxf(acc[i][2] + bb.z, 0.f);
            o.w = fmaxf(acc[i][3] + bb.w, 0.f);
            *reinterpret_cast<float4*>(C + (size_t)row * 128 + cg) = o;
        }
    }
}

// ---------------- pooling ----------------
__global__ void k_zero_pool() {
    int i = blockIdx.x * blockDim.x + threadIdx.x;
    if (i < kG * kD) g_emb[i] = 0.f;
    if (i < kG) g_gcnt[i] = 0;
}

__global__ void k_pool(const float* __restrict__ h, const int* __restrict__ gids) {
    int w = (blockIdx.x * blockDim.x + threadIdx.x) >> 5;
    int lane = threadIdx.x & 31;
    if (w >= kN) return;
    int gid = gids[w];
    float4 x = reinterpret_cast<const float4*>(h + (size_t)w * kD)[lane];
    float* e = g_emb + (size_t)gid * kD + lane * 4;
    atomicAdd(e + 0, x.x);
    atomicAdd(e + 1, x.y);
    atomicAdd(e + 2, x.z);
    atomicAdd(e + 3, x.w);
    if (lane == 0) atomicAdd(&g_gcnt[gid], 1);
}

__global__ void k_pool_norm() {
    int i = blockIdx.x * blockDim.x + threadIdx.x;
    if (i >= kG * kD) return;
    int g = i >> 7;
    float c = (float)max(g_gcnt[g], 1);
    g_emb[i] = g_emb[i] / c;
}

// ---------------- MLP head ----------------
// Y[g][c] = relu(sum_k X[g][k]*W[k][c] + b[c]); 8 graphs per thread (W reuse)
__global__ void k_mlp(const float* __restrict__ X, const float* __restrict__ W,
                      const float* __restrict__ b, float* __restrict__ Y,
                      int K, int M) {
    int idx = blockIdx.x * blockDim.x + threadIdx.x;
    int c = idx % M;
    int g0 = (idx / M) * 8;
    if (g0 >= kG) return;
    float acc[8];
    #pragma unroll
    for (int j = 0; j < 8; ++j) acc[j] = 0.f;
    for (int k = 0; k < K; ++k) {
        float w = W[(size_t)k * M + c];
        #pragma unroll
        for (int j = 0; j < 8; ++j)
            acc[j] += X[(size_t)(g0 + j) * K + k] * w;
    }
    float bias = b[c];
    #pragma unroll
    for (int j = 0; j < 8; ++j)
        Y[(size_t)(g0 + j) * M + c] = fmaxf(acc[j] + bias, 0.f);
}

// final: [kG,256] x [256,1] + b (no relu), warp per graph
__global__ void k_final(const float* __restrict__ X, const float* __restrict__ W,
                        const float* __restrict__ b, float* __restrict__ out) {
    int g = (blockIdx.x * blockDim.x + threadIdx.x) >> 5;
    int lane = threadIdx.x & 31;
    if (g >= kG) return;
    float s = 0.f;
    #pragma unroll
    for (int k = lane; k < 256; k += 32) s += X[(size_t)g * 256 + k] * W[k];
    #pragma unroll
    for (int off = 16; off; off >>= 1) s += __shfl_down_sync(0xffffffffu, s, off);
    if (lane == 0) out[g] = s + b[0];
}

// ---------------- launch ----------------
extern "C" void kernel_launch(void* const* d_in, const int* in_sizes, int n_in,
                              void* d_out, int out_size) {
    const float* feats = (const float*)d_in[0];
    const int*   src   = (const int*)d_in[1];
    const int*   dst   = (const int*)d_in[2];
    const int*   gids  = (const int*)d_in[3];
    const float* W0 = (const float*)d_in[4];  const float* b0 = (const float*)d_in[5];
    const float* W1 = (const float*)d_in[6];  const float* b1 = (const float*)d_in[7];
    const float* W2 = (const float*)d_in[8];  const float* b2 = (const float*)d_in[9];
    const float* Wm0 = (const float*)d_in[10]; const float* bm0 = (const float*)d_in[11];
    const float* Wm1 = (const float*)d_in[12]; const float* bm1 = (const float*)d_in[13];
    const float* Wm2 = (const float*)d_in[14]; const float* bm2 = (const float*)d_in[15];
    float* out = (float*)d_out;

    float *bufA, *bufB, *emb, *x1, *x2;
    cudaGetSymbolAddress((void**)&bufA, g_bufA);
    cudaGetSymbolAddress((void**)&bufB, g_bufB);
    cudaGetSymbolAddress((void**)&emb,  g_emb);
    cudaGetSymbolAddress((void**)&x1,   g_x1);
    cudaGetSymbolAddress((void**)&x2,   g_x2);

    cudaFuncSetAttribute(k_gemm128, cudaFuncAttributeMaxDynamicSharedMemorySize,
                         kGemmSmemBytes);

    const int T = 256;
    int nBlkN = (kN + T - 1) / T;           // 391
    int nBlkE = (kE + T - 1) / T;           // 6250
    int nBlkWarpN = (kN * 32 + T - 1) / T;  // 12500
    int nBlkGemm = (kN + 63) / 64;          // 1563
    int nBlkPoolZ = (kG * kD + T - 1) / T;  // 1024

    // degrees + normalization coefficients
    k_zero_deg<<<nBlkN, T>>>();
    k_degrees<<<nBlkE, T>>>(src, dst);
    k_inv<<<nBlkN, T>>>();

    // CSR-by-dst build
    k_scan1<<<kScanBlocks, 1024>>>();
    k_scan_tops<<<1, 1024>>>();
    k_scan_add<<<nBlkN, T>>>();
    k_scatter<<<nBlkE, T>>>(src, dst);

    // 3 GCN layers: gather -> GEMM(+bias,ReLU)
    k_gather<<<nBlkWarpN, T>>>(feats, bufB);
    k_gemm128<<<nBlkGemm, T, kGemmSmemBytes>>>(bufB, W0, b0, bufA, kN);

    k_gather<<<nBlkWarpN, T>>>(bufA, bufB);
    k_gemm128<<<nBlkGemm, T, kGemmSmemBytes>>>(bufB, W1, b1, bufA, kN);

    k_gather<<<nBlkWarpN, T>>>(bufA, bufB);
    k_gemm128<<<nBlkGemm, T, kGemmSmemBytes>>>(bufB, W2, b2, bufA, kN);

    // average pooling per graph
    k_zero_pool<<<nBlkPoolZ, T>>>();
    k_pool<<<nBlkWarpN, T>>>(bufA, gids);
    k_pool_norm<<<nBlkPoolZ, T>>>();

    // MLP head
    k_mlp<<<(kG / 8) * 512 / T, T>>>(emb, Wm0, bm0, x1, 128, 512);
    k_mlp<<<(kG / 8) * 256 / T, T>>>(x1, Wm1, bm1, x2, 512, 256);
    k_final<<<(kG * 32) / T, T>>>(x2, Wm2, bm2, out);
}